// round 16
// baseline (speedup 1.0000x reference)
#include <cuda_runtime.h>
#include <math.h>

// Problem dims
#define B_  256
#define T_  336
#define I_  16
#define H_  512
#define L_  256
#define O_  10
#define G4  2048   // 4*H

// Recurrence kernel config: 128 CTAs x 4 warps (1 CTA/SM, 1 warp/SMSP)
#define NCTA 128
#define NTHR 128           // 4 warps
#define JPC  4             // h-columns per CTA (H_/NCTA)

typedef unsigned long long u64t;

// ---------------- device scratch ----------------
__device__ float d_Wt[G4 * H_];        // sampled Whh, transposed: [gatecol][k]
__device__ float d_xg[T_ * G4];        // precomputed input projection for b=255
__device__ u64t  d_hh[T_ * H_];        // tagged h history: hi32=epoch(t+1), lo32=h bits
__device__ float d_BLWt[H_ * L_];      // sampled BLW, transposed: [h][l]
__device__ float d_BLb[L_];            // sampled BLb
__device__ float d_Wih_s[I_ * G4];     // sampled Wih
__device__ float d_b_s[G4];            // sampled bias

__device__ __forceinline__ float softplusf(float v) {
    return (v > 20.0f) ? v : log1pf(expf(v));
}
// fast (MUFU-based) activations: rel err ~5e-7, far inside the 1e-3 budget
__device__ __forceinline__ float fsig(float v) {
    return __fdividef(1.0f, 1.0f + __expf(-v));
}
__device__ __forceinline__ float ftanh(float v) {
    return __fdividef(2.0f, 1.0f + __expf(-2.0f * v)) - 1.0f;
}

// ---- packed f32x2 helpers (FFMA2) ----
__device__ __forceinline__ u64t pack2(float x, float y) {
    u64t r; asm("mov.b64 %0, {%1,%2};" : "=l"(r) : "f"(x), "f"(y)); return r;
}
__device__ __forceinline__ float2 unpack2(u64t v) {
    float2 r; asm("mov.b64 {%0,%1}, %2;" : "=f"(r.x), "=f"(r.y) : "l"(v)); return r;
}
__device__ __forceinline__ u64t ffma2(u64t a, u64t b, u64t c) {
    u64t d; asm("fma.rn.f32x2 %0, %1, %2, %3;" : "=l"(d) : "l"(a), "l"(b), "l"(c)); return d;
}

// ---- tear-free 8B tagged-word primitives (gpu scope, L2-coherent) ----
__device__ __forceinline__ void st_relaxed_u64(u64t* p, u64t v) {
    asm volatile("st.relaxed.gpu.global.u64 [%0], %1;" :: "l"(p), "l"(v) : "memory");
}
__device__ __forceinline__ u64t ld_relaxed_u64(const u64t* p) {
    u64t v;
    asm volatile("ld.relaxed.gpu.global.u64 %0, [%1];" : "=l"(v) : "l"(p) : "memory");
    return v;
}

// ---------------- launch #1: clear tagged history + all small sampling ----------------
__global__ void setup_all(const float* __restrict__ wih_mu,
                          const float* __restrict__ wih_rho,
                          const float* __restrict__ eps_wih,
                          const float* __restrict__ b_mu,
                          const float* __restrict__ b_rho,
                          const float* __restrict__ eps_b,
                          const float* __restrict__ blb_mu,
                          const float* __restrict__ blb_rho,
                          const float* __restrict__ eps_blb) {
    const int id = blockIdx.x * blockDim.x + threadIdx.x;
    if (id < T_ * H_) d_hh[id] = 0ull;                  // tag 0 != any epoch 1..T
    if (id < I_ * G4)
        d_Wih_s[id] = wih_mu[id] + softplusf(wih_rho[id]) * eps_wih[id];
    if (id < G4)
        d_b_s[id] = b_mu[id] + softplusf(b_rho[id]) * eps_b[id];
    if (id < L_)
        d_BLb[id] = blb_mu[id] + softplusf(blb_rho[id]) * eps_blb[id];
}

// ---------------- launch #2: BOTH sample+transposes (z selects matrix) ----------------
__global__ void sample_transpose_both(const float* __restrict__ whh_mu,
                                      const float* __restrict__ whh_rho,
                                      const float* __restrict__ eps_whh,
                                      float* __restrict__ wt_out,
                                      const float* __restrict__ blw_mu,
                                      const float* __restrict__ blw_rho,
                                      const float* __restrict__ eps_blw,
                                      float* __restrict__ blwt_out) {
    const float *mu, *rho, *eps;
    float* out;
    int R, C;
    if (blockIdx.z == 0) {            // Whh: [H_ x G4] -> Wt [G4 x H_]
        mu = whh_mu; rho = whh_rho; eps = eps_whh; out = wt_out;
        R = H_; C = G4;
        if (blockIdx.x >= G4 / 32 || blockIdx.y >= H_ / 32) return;
    } else {                          // BLW: [L_ x H_] -> BLWt [H_ x L_]
        mu = blw_mu; rho = blw_rho; eps = eps_blw; out = blwt_out;
        R = L_; C = H_;
        if (blockIdx.x >= H_ / 32 || blockIdx.y >= L_ / 32) return;
    }
    __shared__ float tile[32][33];
    const int c0 = blockIdx.x * 32;
    const int r0 = blockIdx.y * 32;
    const int tx = threadIdx.x, ty = threadIdx.y;
    const int idx = (r0 + ty) * C + (c0 + tx);
    tile[ty][tx] = mu[idx] + softplusf(rho[idx]) * eps[idx];
    __syncthreads();
    out[(c0 + ty) * R + (r0 + tx)] = tile[tx][ty];
}

// ---------------- launch #3: xg[t][g] (parallel over t AND g) ----------------
__global__ void compute_xg(const float* __restrict__ x,
                           const float* __restrict__ drop_x) {
    const int g = blockIdx.x * blockDim.x + threadIdx.x;
    const int t = blockIdx.y;
    const float* xr = x      + ((size_t)255 * T_ + t) * I_;
    const float* dr = drop_x + ((size_t)255 * T_ + t) * I_;
    float acc = d_b_s[g];
#pragma unroll
    for (int i = 0; i < I_; i++)
        acc = fmaf(xr[i] * dr[i], d_Wih_s[i * G4 + g], acc);
    d_xg[t * G4 + g] = acc;
}

// ---------------- launch #4 (ncu slot): recurrence, batch row 255 only ----------------
// 128 CTAs x 4 warps. Two-wave software-pipelined burst poll: wave B is issued
// BEFORE wave A is checked, halving the effective re-check period (~RT/2).
// xg broadcast + accumulator init hoisted BEFORE the poll (depend only on the
// prefetch issued a full step earlier).
__global__ void __launch_bounds__(NTHR, 1) lstm_recurrence() {
    __shared__ float sh_h[2][H_];          // double buffer by row parity

    const int warp = threadIdx.x >> 5;     // 0..3
    const int lane = threadIdx.x & 31;
    const int j    = blockIdx.x * JPC + warp;   // owned h-column, 0..511

    // Register-resident packed weights: pair p = (k=2p, 2p+1), p-index = kk*32+lane
    u64t W0[8], W1[8], W2[8], W3[8];
    {
        const float2* r0 = (const float2*)(d_Wt + (size_t)(j          ) * H_);
        const float2* r1 = (const float2*)(d_Wt + (size_t)(j +     H_ ) * H_);
        const float2* r2 = (const float2*)(d_Wt + (size_t)(j + 2 * H_ ) * H_);
        const float2* r3 = (const float2*)(d_Wt + (size_t)(j + 3 * H_ ) * H_);
#pragma unroll
        for (int kk = 0; kk < 8; kk++) {
            const int p = kk * 32 + lane;
            float2 w;
            w = r0[p]; W0[kk] = pack2(w.x, w.y);
            w = r1[p]; W1[kk] = pack2(w.x, w.y);
            w = r2[p]; W2[kk] = pack2(w.x, w.y);
            w = r3[p]; W3[kk] = pack2(w.x, w.y);
        }
    }

    float cstate = 0.0f;   // replicated in ALL lanes

    // xg for t=0: load + broadcast pre-loop (cold start, off any critical path)
    float myxg = (lane < 4) ? __ldg(&d_xg[j + lane * H_]) : 0.0f;
    float xg0 = __shfl_sync(0xffffffffu, myxg, 0);
    float xg1 = __shfl_sync(0xffffffffu, myxg, 1);
    float xg2 = __shfl_sync(0xffffffffu, myxg, 2);
    float xg3 = __shfl_sync(0xffffffffu, myxg, 3);

#pragma unroll 1
    for (int t = 0; t < T_; t++) {
        float s0, s1, s2, s3;
        if (t == 0) {
            s0 = xg0; s1 = xg1; s2 = xg2; s3 = xg3;
        } else {
            // Hoisted xg broadcast (prefetch LDG issued a full step ago) +
            // lane-0 accumulator init — both independent of the h row.
            xg0 = __shfl_sync(0xffffffffu, myxg, 0);
            xg1 = __shfl_sync(0xffffffffu, myxg, 1);
            xg2 = __shfl_sync(0xffffffffu, myxg, 2);
            xg3 = __shfl_sync(0xffffffffu, myxg, 3);
            u64t a0 = (lane == 0) ? pack2(xg0, 0.0f) : 0ull;
            u64t a1 = (lane == 0) ? pack2(xg1, 0.0f) : 0ull;
            u64t a2 = (lane == 0) ? pack2(xg2, 0.0f) : 0ull;
            u64t a3 = (lane == 0) ? pack2(xg3, 0.0f) : 0ull;

            const int buf = (t - 1) & 1;
            // ---- two-wave pipelined poll: each warp owns a quarter of row t-1 ----
            {
                const u64t* hp = d_hh + (size_t)(t - 1) * H_ + warp * 128;
                const unsigned want = (unsigned)t;   // epoch tag for row t-1
                u64t vA[4], vB[4];
#pragma unroll
                for (int kk = 0; kk < 4; kk++)
                    vA[kk] = ld_relaxed_u64(hp + kk * 32 + lane);
                for (;;) {
                    // issue wave B before checking wave A
#pragma unroll
                    for (int kk = 0; kk < 4; kk++)
                        vB[kk] = ld_relaxed_u64(hp + kk * 32 + lane);
                    unsigned accA = 0u;
#pragma unroll
                    for (int kk = 0; kk < 4; kk++)
                        accA |= ((unsigned)(vA[kk] >> 32)) ^ want;
                    if (!__any_sync(0xffffffffu, accA != 0u)) {
#pragma unroll
                        for (int kk = 0; kk < 4; kk++)
                            sh_h[buf][(warp * 4 + kk) * 32 + lane] =
                                __uint_as_float((unsigned)vA[kk]);
                        break;
                    }
                    // re-issue wave A before checking wave B
#pragma unroll
                    for (int kk = 0; kk < 4; kk++)
                        vA[kk] = ld_relaxed_u64(hp + kk * 32 + lane);
                    unsigned accB = 0u;
#pragma unroll
                    for (int kk = 0; kk < 4; kk++)
                        accB |= ((unsigned)(vB[kk] >> 32)) ^ want;
                    if (!__any_sync(0xffffffffu, accB != 0u)) {
#pragma unroll
                        for (int kk = 0; kk < 4; kk++)
                            sh_h[buf][(warp * 4 + kk) * 32 + lane] =
                                __uint_as_float((unsigned)vB[kk]);
                        break;
                    }
                }
            }
            __syncthreads();   // 4-warp bar: SMEM h row visible to all warps

            // ---- compute from SMEM (LDS.64, conflict-free) ----
            const float2* hp2 = (const float2*)sh_h[buf];
#pragma unroll
            for (int kk = 0; kk < 8; kk++) {
                const float2 hv = hp2[kk * 32 + lane];
                const u64t hw = pack2(hv.x, hv.y);
                a0 = ffma2(W0[kk], hw, a0);
                a1 = ffma2(W1[kk], hw, a1);
                a2 = ffma2(W2[kk], hw, a2);
                a3 = ffma2(W3[kk], hw, a3);
            }
            const float2 f0 = unpack2(a0), f1 = unpack2(a1),
                         f2 = unpack2(a2), f3 = unpack2(a3);
            s0 = f0.x + f0.y; s1 = f1.x + f1.y;
            s2 = f2.x + f2.y; s3 = f3.x + f3.y;
#pragma unroll
            for (int off = 16; off > 0; off >>= 1) {
                s0 += __shfl_xor_sync(0xffffffffu, s0, off);
                s1 += __shfl_xor_sync(0xffffffffu, s1, off);
                s2 += __shfl_xor_sync(0xffffffffu, s2, off);
                s3 += __shfl_xor_sync(0xffffffffu, s3, off);
            }
        }

        // all-lane redundant gating (xg already folded into s0..s3)
        const float iv = fsig (s0);
        const float fv = fsig (s1);
        const float gv = ftanh(s2);
        const float ov = fsig (s3);
        cstate = fv * cstate + iv * gv;
        const float hval = ov * ftanh(cstate);
        if (lane == 0) {
            // publish tagged {epoch = t+1, h} in one tear-free 8B store
            const u64t pk = ((u64t)(unsigned)(t + 1) << 32) |
                            (u64t)__float_as_uint(hval);
            st_relaxed_u64(&d_hh[(size_t)t * H_ + j], pk);
        }

        // prefetch next step's xg: LDG ISSUE ONLY (broadcast deferred to next iter)
        if (t + 1 < T_)
            myxg = (lane < 4) ? __ldg(&d_xg[(t + 1) * G4 + j + lane * H_]) : 0.0f;
        // No end-of-step barrier: parity double buffer prevents overwrite hazards;
        // the next iteration's __syncthreads orders pollers vs consumers.
    }
}

// ---------------- launch #5: epilogue ----------------
#define BPB 4
__global__ void epilogue(const float* __restrict__ drop_h,
                         const float* __restrict__ drop_l,
                         const float* __restrict__ lin_w,
                         float* __restrict__ out) {
    __shared__ float hv[BPB][H_];
    __shared__ float ys[BPB][L_];
    const int bp0 = blockIdx.x * BPB;
    const int tid = threadIdx.x;

    for (int e = tid; e < BPB * H_; e += blockDim.x) {
        const int bb = e / H_, h = e % H_;
        const int bp = bp0 + bb;
        const float hval = __uint_as_float((unsigned)d_hh[(size_t)(80 + bp) * H_ + h]);
        hv[bb][h] = hval * drop_h[(size_t)bp * H_ + h];
    }
    __syncthreads();

    const int l = tid;   // 256 threads == L_
    float a0 = d_BLb[l], a1 = a0, a2 = a0, a3 = a0;
    for (int h = 0; h < H_; h++) {
        const float w = d_BLWt[h * L_ + l];
        a0 = fmaf(hv[0][h], w, a0);
        a1 = fmaf(hv[1][h], w, a1);
        a2 = fmaf(hv[2][h], w, a2);
        a3 = fmaf(hv[3][h], w, a3);
    }
    ys[0][l] = fmaxf(a0, 0.f) * drop_l[(size_t)(bp0 + 0) * L_ + l];
    ys[1][l] = fmaxf(a1, 0.f) * drop_l[(size_t)(bp0 + 1) * L_ + l];
    ys[2][l] = fmaxf(a2, 0.f) * drop_l[(size_t)(bp0 + 2) * L_ + l];
    ys[3][l] = fmaxf(a3, 0.f) * drop_l[(size_t)(bp0 + 3) * L_ + l];
    __syncthreads();

    if (tid < 32) {
        for (int bb = 0; bb < BPB; bb++) {
            for (int o = 0; o < O_; o++) {
                float a = 0.f;
                for (int ll = tid; ll < L_; ll += 32)
                    a = fmaf(ys[bb][ll], lin_w[o * L_ + ll], a);
#pragma unroll
                for (int off = 16; off > 0; off >>= 1)
                    a += __shfl_xor_sync(0xffffffffu, a, off);
                if (tid == 0) out[(size_t)(bp0 + bb) * O_ + o] = a;
            }
        }
    }
}

// ---------------- launcher ----------------
extern "C" void kernel_launch(void* const* d_in, const int* in_sizes, int n_in,
                              void* d_out, int out_size) {
    const float* x        = (const float*)d_in[0];
    const float* drop_x   = (const float*)d_in[1];
    const float* drop_h   = (const float*)d_in[2];
    const float* drop_l   = (const float*)d_in[3];
    const float* wih_mu   = (const float*)d_in[4];
    const float* wih_rho  = (const float*)d_in[5];
    const float* eps_wih  = (const float*)d_in[6];
    const float* whh_mu   = (const float*)d_in[7];
    const float* whh_rho  = (const float*)d_in[8];
    const float* eps_whh  = (const float*)d_in[9];
    const float* b_mu     = (const float*)d_in[10];
    const float* b_rho    = (const float*)d_in[11];
    const float* eps_b    = (const float*)d_in[12];
    const float* blw_mu   = (const float*)d_in[13];
    const float* blw_rho  = (const float*)d_in[14];
    const float* eps_blw  = (const float*)d_in[15];
    const float* blb_mu   = (const float*)d_in[16];
    const float* blb_rho  = (const float*)d_in[17];
    const float* eps_blb  = (const float*)d_in[18];
    const float* lin_w    = (const float*)d_in[19];
    float* out = (float*)d_out;

    float* wt_ptr   = nullptr;
    float* blwt_ptr = nullptr;
    cudaGetSymbolAddress((void**)&wt_ptr,   d_Wt);
    cudaGetSymbolAddress((void**)&blwt_ptr, d_BLWt);

    // Launch order keeps the recurrence at slot #4 (ncu capture slot).
    setup_all<<<(T_ * H_ + 255) / 256, 256>>>(
        wih_mu, wih_rho, eps_wih, b_mu, b_rho, eps_b, blb_mu, blb_rho, eps_blb);
    sample_transpose_both<<<dim3(G4 / 32, H_ / 32, 2), dim3(32, 32)>>>(
        whh_mu, whh_rho, eps_whh, wt_ptr, blw_mu, blw_rho, eps_blw, blwt_ptr);
    compute_xg<<<dim3(G4 / 256, T_), 256>>>(x, drop_x);
    lstm_recurrence<<<NCTA, NTHR>>>();
    epilogue<<<L_ / BPB, 256>>>(drop_h, drop_l, lin_w, out);
}

// round 17
// speedup vs baseline: 1.0886x; 1.0886x over previous
#include <cuda_runtime.h>
#include <math.h>

// Problem dims
#define B_  256
#define T_  336
#define I_  16
#define H_  512
#define L_  256
#define O_  10
#define G4  2048   // 4*H

// Recurrence kernel config: 128 CTAs x 4 warps (1 CTA/SM, 1 warp/SMSP)
#define NCTA 128
#define NTHR 128           // 4 warps
#define JPC  4             // h-columns per CTA (H_/NCTA)

typedef unsigned long long u64t;

// ---------------- device scratch ----------------
__device__ float d_Wt[G4 * H_];        // sampled Whh, transposed: [gatecol][k]
__device__ float d_xg[T_ * G4];        // precomputed input projection for b=255
__device__ u64t  d_hh[T_ * H_];        // tagged h history: hi32=epoch(t+1), lo32=h bits
__device__ float d_BLWt[H_ * L_];      // sampled BLW, transposed: [h][l]
__device__ float d_BLb[L_];            // sampled BLb
__device__ float d_Wih_s[I_ * G4];     // sampled Wih
__device__ float d_b_s[G4];            // sampled bias

__device__ __forceinline__ float softplusf(float v) {
    return (v > 20.0f) ? v : log1pf(expf(v));
}
// fast (MUFU-based) activations: rel err ~5e-7, far inside the 1e-3 budget
__device__ __forceinline__ float fsig(float v) {
    return __fdividef(1.0f, 1.0f + __expf(-v));
}
__device__ __forceinline__ float ftanh(float v) {
    return __fdividef(2.0f, 1.0f + __expf(-2.0f * v)) - 1.0f;
}

// ---- packed f32x2 helpers (FFMA2) ----
__device__ __forceinline__ u64t pack2(float x, float y) {
    u64t r; asm("mov.b64 %0, {%1,%2};" : "=l"(r) : "f"(x), "f"(y)); return r;
}
__device__ __forceinline__ float2 unpack2(u64t v) {
    float2 r; asm("mov.b64 {%0,%1}, %2;" : "=f"(r.x), "=f"(r.y) : "l"(v)); return r;
}
__device__ __forceinline__ u64t ffma2(u64t a, u64t b, u64t c) {
    u64t d; asm("fma.rn.f32x2 %0, %1, %2, %3;" : "=l"(d) : "l"(a), "l"(b), "l"(c)); return d;
}

// ---- tear-free 8B tagged-word primitives (gpu scope, L2-coherent) ----
__device__ __forceinline__ void st_relaxed_u64(u64t* p, u64t v) {
    asm volatile("st.relaxed.gpu.global.u64 [%0], %1;" :: "l"(p), "l"(v) : "memory");
}
__device__ __forceinline__ u64t ld_relaxed_u64(const u64t* p) {
    u64t v;
    asm volatile("ld.relaxed.gpu.global.u64 %0, [%1];" : "=l"(v) : "l"(p) : "memory");
    return v;
}

// ---------------- launch #1: clear tagged history + all small sampling ----------------
__global__ void setup_all(const float* __restrict__ wih_mu,
                          const float* __restrict__ wih_rho,
                          const float* __restrict__ eps_wih,
                          const float* __restrict__ b_mu,
                          const float* __restrict__ b_rho,
                          const float* __restrict__ eps_b,
                          const float* __restrict__ blb_mu,
                          const float* __restrict__ blb_rho,
                          const float* __restrict__ eps_blb) {
    const int id = blockIdx.x * blockDim.x + threadIdx.x;
    if (id < T_ * H_) d_hh[id] = 0ull;                  // tag 0 != any epoch 1..T
    if (id < I_ * G4)
        d_Wih_s[id] = wih_mu[id] + softplusf(wih_rho[id]) * eps_wih[id];
    if (id < G4)
        d_b_s[id] = b_mu[id] + softplusf(b_rho[id]) * eps_b[id];
    if (id < L_)
        d_BLb[id] = blb_mu[id] + softplusf(blb_rho[id]) * eps_blb[id];
}

// ---------------- launch #2: BOTH sample+transposes (z selects matrix) ----------------
__global__ void sample_transpose_both(const float* __restrict__ whh_mu,
                                      const float* __restrict__ whh_rho,
                                      const float* __restrict__ eps_whh,
                                      float* __restrict__ wt_out,
                                      const float* __restrict__ blw_mu,
                                      const float* __restrict__ blw_rho,
                                      const float* __restrict__ eps_blw,
                                      float* __restrict__ blwt_out) {
    const float *mu, *rho, *eps;
    float* out;
    int R, C;
    if (blockIdx.z == 0) {            // Whh: [H_ x G4] -> Wt [G4 x H_]
        mu = whh_mu; rho = whh_rho; eps = eps_whh; out = wt_out;
        R = H_; C = G4;
        if (blockIdx.x >= G4 / 32 || blockIdx.y >= H_ / 32) return;
    } else {                          // BLW: [L_ x H_] -> BLWt [H_ x L_]
        mu = blw_mu; rho = blw_rho; eps = eps_blw; out = blwt_out;
        R = L_; C = H_;
        if (blockIdx.x >= H_ / 32 || blockIdx.y >= L_ / 32) return;
    }
    __shared__ float tile[32][33];
    const int c0 = blockIdx.x * 32;
    const int r0 = blockIdx.y * 32;
    const int tx = threadIdx.x, ty = threadIdx.y;
    const int idx = (r0 + ty) * C + (c0 + tx);
    tile[ty][tx] = mu[idx] + softplusf(rho[idx]) * eps[idx];
    __syncthreads();
    out[(c0 + ty) * R + (r0 + tx)] = tile[tx][ty];
}

// ---------------- launch #3: xg[t][g] (parallel over t AND g) ----------------
__global__ void compute_xg(const float* __restrict__ x,
                           const float* __restrict__ drop_x) {
    const int g = blockIdx.x * blockDim.x + threadIdx.x;
    const int t = blockIdx.y;
    const float* xr = x      + ((size_t)255 * T_ + t) * I_;
    const float* dr = drop_x + ((size_t)255 * T_ + t) * I_;
    float acc = d_b_s[g];
#pragma unroll
    for (int i = 0; i < I_; i++)
        acc = fmaf(xr[i] * dr[i], d_Wih_s[i * G4 + g], acc);
    d_xg[t * G4 + g] = acc;
}

// ---------------- launch #4 (ncu slot): recurrence, batch row 255 only ----------------
// 128 CTAs x 4 warps. SINGLE-WAVE burst poll (R15 — minimum poll traffic wins)
// with the xg broadcast + accumulator init hoisted BEFORE the poll (R16's one
// good change: both depend only on the prefetch issued a full step earlier).
__global__ void __launch_bounds__(NTHR, 1) lstm_recurrence() {
    __shared__ float sh_h[2][H_];          // double buffer by row parity

    const int warp = threadIdx.x >> 5;     // 0..3
    const int lane = threadIdx.x & 31;
    const int j    = blockIdx.x * JPC + warp;   // owned h-column, 0..511

    // Register-resident packed weights: pair p = (k=2p, 2p+1), p-index = kk*32+lane
    u64t W0[8], W1[8], W2[8], W3[8];
    {
        const float2* r0 = (const float2*)(d_Wt + (size_t)(j          ) * H_);
        const float2* r1 = (const float2*)(d_Wt + (size_t)(j +     H_ ) * H_);
        const float2* r2 = (const float2*)(d_Wt + (size_t)(j + 2 * H_ ) * H_);
        const float2* r3 = (const float2*)(d_Wt + (size_t)(j + 3 * H_ ) * H_);
#pragma unroll
        for (int kk = 0; kk < 8; kk++) {
            const int p = kk * 32 + lane;
            float2 w;
            w = r0[p]; W0[kk] = pack2(w.x, w.y);
            w = r1[p]; W1[kk] = pack2(w.x, w.y);
            w = r2[p]; W2[kk] = pack2(w.x, w.y);
            w = r3[p]; W3[kk] = pack2(w.x, w.y);
        }
    }

    float cstate = 0.0f;   // replicated in ALL lanes

    // xg for t=0: load + broadcast pre-loop (cold start, off any critical path)
    float myxg = (lane < 4) ? __ldg(&d_xg[j + lane * H_]) : 0.0f;
    float xg0 = __shfl_sync(0xffffffffu, myxg, 0);
    float xg1 = __shfl_sync(0xffffffffu, myxg, 1);
    float xg2 = __shfl_sync(0xffffffffu, myxg, 2);
    float xg3 = __shfl_sync(0xffffffffu, myxg, 3);

#pragma unroll 1
    for (int t = 0; t < T_; t++) {
        float s0, s1, s2, s3;
        if (t == 0) {
            s0 = xg0; s1 = xg1; s2 = xg2; s3 = xg3;
        } else {
            // Hoisted xg broadcast (prefetch LDG issued a full step ago) +
            // lane-0 accumulator init — both independent of the h row.
            xg0 = __shfl_sync(0xffffffffu, myxg, 0);
            xg1 = __shfl_sync(0xffffffffu, myxg, 1);
            xg2 = __shfl_sync(0xffffffffu, myxg, 2);
            xg3 = __shfl_sync(0xffffffffu, myxg, 3);
            u64t a0 = (lane == 0) ? pack2(xg0, 0.0f) : 0ull;
            u64t a1 = (lane == 0) ? pack2(xg1, 0.0f) : 0ull;
            u64t a2 = (lane == 0) ? pack2(xg2, 0.0f) : 0ull;
            u64t a3 = (lane == 0) ? pack2(xg3, 0.0f) : 0ull;

            const int buf = (t - 1) & 1;
            // ---- single-wave burst poll: every warp owns a quarter of row t-1 ----
            {
                const u64t* hp = d_hh + (size_t)(t - 1) * H_;
                const unsigned want = (unsigned)t;   // epoch tag for row t-1
                u64t v[4];
                unsigned anybad;
                do {
#pragma unroll
                    for (int kk = 0; kk < 4; kk++)
                        v[kk] = ld_relaxed_u64(hp + (warp * 4 + kk) * 32 + lane);  // MLP=4
                    unsigned acc = 0u;
#pragma unroll
                    for (int kk = 0; kk < 4; kk++)
                        acc |= ((unsigned)(v[kk] >> 32)) ^ want;
                    anybad = __any_sync(0xffffffffu, acc != 0u);
                } while (anybad);
#pragma unroll
                for (int kk = 0; kk < 4; kk++)
                    sh_h[buf][(warp * 4 + kk) * 32 + lane] = __uint_as_float((unsigned)v[kk]);
            }
            __syncthreads();   // 4-warp bar: SMEM h row visible to all warps

            // ---- compute from SMEM (LDS.64, conflict-free) ----
            const float2* hp2 = (const float2*)sh_h[buf];
#pragma unroll
            for (int kk = 0; kk < 8; kk++) {
                const float2 hv = hp2[kk * 32 + lane];
                const u64t hw = pack2(hv.x, hv.y);
                a0 = ffma2(W0[kk], hw, a0);
                a1 = ffma2(W1[kk], hw, a1);
                a2 = ffma2(W2[kk], hw, a2);
                a3 = ffma2(W3[kk], hw, a3);
            }
            const float2 f0 = unpack2(a0), f1 = unpack2(a1),
                         f2 = unpack2(a2), f3 = unpack2(a3);
            s0 = f0.x + f0.y; s1 = f1.x + f1.y;
            s2 = f2.x + f2.y; s3 = f3.x + f3.y;
#pragma unroll
            for (int off = 16; off > 0; off >>= 1) {
                s0 += __shfl_xor_sync(0xffffffffu, s0, off);
                s1 += __shfl_xor_sync(0xffffffffu, s1, off);
                s2 += __shfl_xor_sync(0xffffffffu, s2, off);
                s3 += __shfl_xor_sync(0xffffffffu, s3, off);
            }
        }

        // all-lane redundant gating (xg already folded into s0..s3)
        const float iv = fsig (s0);
        const float fv = fsig (s1);
        const float gv = ftanh(s2);
        const float ov = fsig (s3);
        cstate = fv * cstate + iv * gv;
        const float hval = ov * ftanh(cstate);
        if (lane == 0) {
            // publish tagged {epoch = t+1, h} in one tear-free 8B store
            const u64t pk = ((u64t)(unsigned)(t + 1) << 32) |
                            (u64t)__float_as_uint(hval);
            st_relaxed_u64(&d_hh[(size_t)t * H_ + j], pk);
        }

        // prefetch next step's xg: LDG ISSUE ONLY (broadcast deferred to next iter)
        if (t + 1 < T_)
            myxg = (lane < 4) ? __ldg(&d_xg[(t + 1) * G4 + j + lane * H_]) : 0.0f;
        // No end-of-step barrier: parity double buffer prevents overwrite hazards;
        // the next iteration's __syncthreads orders pollers vs consumers.
    }
}

// ---------------- launch #5: epilogue ----------------
#define BPB 4
__global__ void epilogue(const float* __restrict__ drop_h,
                         const float* __restrict__ drop_l,
                         const float* __restrict__ lin_w,
                         float* __restrict__ out) {
    __shared__ float hv[BPB][H_];
    __shared__ float ys[BPB][L_];
    const int bp0 = blockIdx.x * BPB;
    const int tid = threadIdx.x;

    for (int e = tid; e < BPB * H_; e += blockDim.x) {
        const int bb = e / H_, h = e % H_;
        const int bp = bp0 + bb;
        const float hval = __uint_as_float((unsigned)d_hh[(size_t)(80 + bp) * H_ + h]);
        hv[bb][h] = hval * drop_h[(size_t)bp * H_ + h];
    }
    __syncthreads();

    const int l = tid;   // 256 threads == L_
    float a0 = d_BLb[l], a1 = a0, a2 = a0, a3 = a0;
    for (int h = 0; h < H_; h++) {
        const float w = d_BLWt[h * L_ + l];
        a0 = fmaf(hv[0][h], w, a0);
        a1 = fmaf(hv[1][h], w, a1);
        a2 = fmaf(hv[2][h], w, a2);
        a3 = fmaf(hv[3][h], w, a3);
    }
    ys[0][l] = fmaxf(a0, 0.f) * drop_l[(size_t)(bp0 + 0) * L_ + l];
    ys[1][l] = fmaxf(a1, 0.f) * drop_l[(size_t)(bp0 + 1) * L_ + l];
    ys[2][l] = fmaxf(a2, 0.f) * drop_l[(size_t)(bp0 + 2) * L_ + l];
    ys[3][l] = fmaxf(a3, 0.f) * drop_l[(size_t)(bp0 + 3) * L_ + l];
    __syncthreads();

    if (tid < 32) {
        for (int bb = 0; bb < BPB; bb++) {
            for (int o = 0; o < O_; o++) {
                float a = 0.f;
                for (int ll = tid; ll < L_; ll += 32)
                    a = fmaf(ys[bb][ll], lin_w[o * L_ + ll], a);
#pragma unroll
                for (int off = 16; off > 0; off >>= 1)
                    a += __shfl_xor_sync(0xffffffffu, a, off);
                if (tid == 0) out[(size_t)(bp0 + bb) * O_ + o] = a;
            }
        }
    }
}

// ---------------- launcher ----------------
extern "C" void kernel_launch(void* const* d_in, const int* in_sizes, int n_in,
                              void* d_out, int out_size) {
    const float* x        = (const float*)d_in[0];
    const float* drop_x   = (const float*)d_in[1];
    const float* drop_h   = (const float*)d_in[2];
    const float* drop_l   = (const float*)d_in[3];
    const float* wih_mu   = (const float*)d_in[4];
    const float* wih_rho  = (const float*)d_in[5];
    const float* eps_wih  = (const float*)d_in[6];
    const float* whh_mu   = (const float*)d_in[7];
    const float* whh_rho  = (const float*)d_in[8];
    const float* eps_whh  = (const float*)d_in[9];
    const float* b_mu     = (const float*)d_in[10];
    const float* b_rho    = (const float*)d_in[11];
    const float* eps_b    = (const float*)d_in[12];
    const float* blw_mu   = (const float*)d_in[13];
    const float* blw_rho  = (const float*)d_in[14];
    const float* eps_blw  = (const float*)d_in[15];
    const float* blb_mu   = (const float*)d_in[16];
    const float* blb_rho  = (const float*)d_in[17];
    const float* eps_blb  = (const float*)d_in[18];
    const float* lin_w    = (const float*)d_in[19];
    float* out = (float*)d_out;

    float* wt_ptr   = nullptr;
    float* blwt_ptr = nullptr;
    cudaGetSymbolAddress((void**)&wt_ptr,   d_Wt);
    cudaGetSymbolAddress((void**)&blwt_ptr, d_BLWt);

    // Launch order keeps the recurrence at slot #4 (ncu capture slot).
    setup_all<<<(T_ * H_ + 255) / 256, 256>>>(
        wih_mu, wih_rho, eps_wih, b_mu, b_rho, eps_b, blb_mu, blb_rho, eps_blb);
    sample_transpose_both<<<dim3(G4 / 32, H_ / 32, 2), dim3(32, 32)>>>(
        whh_mu, whh_rho, eps_whh, wt_ptr, blw_mu, blw_rho, eps_blw, blwt_ptr);
    compute_xg<<<dim3(G4 / 256, T_), 256>>>(x, drop_x);
    lstm_recurrence<<<NCTA, NTHR>>>();
    epilogue<<<L_ / BPB, 256>>>(drop_h, drop_l, lin_w, out);
}